// round 8
// baseline (speedup 1.0000x reference)
#include <cuda_runtime.h>
#include <cuda_fp16.h>

// HashGrid1D on GB300 — R8.
// Warp-cooperative output: lane owns output float4 cells (point p, chunk c)
// = levels 2c,2c+1 of point p; x_p via shfl; results go registers->coalesced
// STG.128 directly. No smem staging (saves 6KB/warp-iter crossbar traffic).
// smem = 98.3KB (levels 0..8 pairs + level 9) -> 2 CTAs x 1024 = full occ.
// Levels 10+11: one fused gather table indexed by unhashed i11 (L2-resident).

#define HASH_MASK 16383
#define COMB_N    32769
#define SMEM_PAIRS 8185             // sum_{l=0}^{8} ((16<<l)+1)
#define L9_ENTRIES 8194
#define TBL_SCALE     16384.0f
#define TBL_INV_SCALE 6.103515625e-05f  // exact 2^-14
#define PAIR_BYTES  65488           // 8185*8 padded to 16
#define SMEM_TOTAL  (PAIR_BYTES + 32784)   // + 8194*4 padded = 98272

__device__ uint4 g_comb[COMB_N];   // {h2 e10[i10h], h2 e10[i10h+1], h2 e11[i11h], h2 e11[i11h+1]}

__device__ __forceinline__ unsigned pack_h2(float2 a)
{
    __half2 h = __floats2half2_rn(a.x * TBL_SCALE, a.y * TBL_SCALE);
    return *reinterpret_cast<unsigned*>(&h);
}

__device__ __forceinline__ float2 lerp_h2pair(unsigned u0, unsigned u1, float w)
{
    float2 e0 = __half22float2(*reinterpret_cast<__half2*>(&u0));
    float2 e1 = __half22float2(*reinterpret_cast<__half2*>(&u1));
    float2 r;
    r.x = fmaf(w, e1.x - e0.x, e0.x) * TBL_INV_SCALE;
    r.y = fmaf(w, e1.y - e0.y, e0.y) * TBL_INV_SCALE;
    return r;
}

__global__ void build_comb_kernel(const float* __restrict__ table)
{
    int j = blockIdx.x * blockDim.x + threadIdx.x;
    if (j >= COMB_N) return;
    int i10 = j >> 1;
    uint4 v;
    v.x = pack_h2(*reinterpret_cast<const float2*>(table + (i10 & HASH_MASK)       * 24 + 20));
    v.y = pack_h2(*reinterpret_cast<const float2*>(table + ((i10 + 1) & HASH_MASK) * 24 + 20));
    v.z = pack_h2(*reinterpret_cast<const float2*>(table + (j & HASH_MASK)         * 24 + 22));
    v.w = pack_h2(*reinterpret_cast<const float2*>(table + ((j + 1) & HASH_MASK)   * 24 + 22));
    g_comb[j] = v;
}

__global__ void __launch_bounds__(1024, 2)
hashgrid1d_kernel(const float* __restrict__ x,
                  const float* __restrict__ table,
                  float* __restrict__ out,
                  int n)
{
    extern __shared__ unsigned char smem_raw[];
    uint2*    spair = reinterpret_cast<uint2*>(smem_raw);                 // lvl 0..8 pairs
    unsigned* s9    = reinterpret_cast<unsigned*>(smem_raw + PAIR_BYTES); // lvl 9 half2

    const int off[10] = {0, 17, 50, 115, 244, 501, 1014, 2039, 4088, 8185};

    // ---- one-time fills ----
    for (int e = threadIdx.x; e < SMEM_PAIRS; e += blockDim.x) {
        int l = 0;
        #pragma unroll
        for (int k = 1; k < 9; ++k) l += (e >= off[k]);
        int i = e - off[l];
        uint2 v;
        v.x = pack_h2(*reinterpret_cast<const float2*>(table + i       * 24 + 2 * l));
        v.y = pack_h2(*reinterpret_cast<const float2*>(table + (i + 1) * 24 + 2 * l));
        spair[e] = v;
    }
    for (int i = threadIdx.x; i < L9_ENTRIES; i += blockDim.x)
        s9[i] = pack_h2(*reinterpret_cast<const float2*>(table + i * 24 + 18));
    __syncthreads();

    const int lane = threadIdx.x & 31;
    int gwarp  = (blockIdx.x * blockDim.x + threadIdx.x) >> 5;
    int nwarps = (gridDim.x * blockDim.x) >> 5;

    for (int b0 = gwarp * 32; b0 < n; b0 += nwarps * 32) {
        int bi = b0 + lane;
        float xv = (bi < n) ? x[bi] : 0.0f;
        float xc = fminf(fmaxf(xv, 0.0f), 1.0f);

        float4* ob = reinterpret_cast<float4*>(out + (size_t)b0 * 24);

        #pragma unroll
        for (int k = 0; k < 6; ++k) {
            int   w4 = lane + 32 * k;             // 0..191
            int   p  = (w4 * 2731) >> 14;         // w4 / 6
            int   c  = w4 - 6 * p;                // chunk -> levels 2c, 2c+1
            float xp = __shfl_sync(0xffffffffu, xc, p);

            // ---- gather path (c==5 -> levels 10,11); others broadcast idx 0
            float pos11 = xp * 32768.0f;
            int   i11   = __float2int_rd(pos11);
            float w11   = pos11 - (float)i11;
            int   i10   = i11 >> 1;
            float pos10 = pos11 * 0.5f;
            float w10   = pos10 - (float)i10;
            uint4 g     = __ldg(&g_comb[(c == 5) ? i11 : 0]);

            // ---- spair path for level l0 = 2c (clamped: c==5 lanes harmless)
            int   l0   = (c < 5) ? 2 * c : 8;
            float res0 = (float)(16 << l0);
            int   of0  = ((16 << l0) - 16) + l0;  // 16*(2^l0 - 1) + l0
            float pos0 = xp * res0;
            int   i0   = __float2int_rd(pos0);
            float w0   = pos0 - (float)i0;
            uint2 v0   = spair[of0 + i0];

            // ---- spair path for level l1 = 2c+1 (valid c<=3; clamp else)
            int   l1   = (c < 4) ? 2 * c + 1 : 7;
            float res1 = (float)(16 << l1);
            int   of1  = ((16 << l1) - 16) + l1;
            float pos1 = xp * res1;
            int   i1   = __float2int_rd(pos1);
            float w1   = pos1 - (float)i1;
            uint2 v1   = spair[of1 + i1];

            // ---- level 9 path (c==4); others broadcast idx 0
            float pos9 = xp * 8192.0f;
            int   i9r  = __float2int_rd(pos9);
            float w9   = pos9 - (float)i9r;
            int   i9   = (c == 4) ? i9r : 0;
            unsigned u9a = s9[i9];
            unsigned u9b = s9[i9 + 1];

            float2 rg0 = lerp_h2pair(g.x, g.y, w10);
            float2 rg1 = lerp_h2pair(g.z, g.w, w11);
            float2 rs0 = lerp_h2pair(v0.x, v0.y, w0);
            float2 rs1 = lerp_h2pair(v1.x, v1.y, w1);
            float2 r9  = lerp_h2pair(u9a, u9b, w9);

            float2 r0 = (c == 5) ? rg0 : rs0;
            float2 r1 = (c == 5) ? rg1 : ((c == 4) ? r9 : rs1);

            if (b0 + p < n)
                ob[w4] = make_float4(r0.x, r0.y, r1.x, r1.y);
        }
    }
}

extern "C" void kernel_launch(void* const* d_in, const int* in_sizes, int n_in,
                              void* d_out, int out_size)
{
    const float* x     = (const float*)d_in[0];
    const float* table = (const float*)d_in[1];
    float*       out   = (float*)d_out;
    int n = in_sizes[0];

    cudaFuncSetAttribute(hashgrid1d_kernel,
                         cudaFuncAttributeMaxDynamicSharedMemorySize, SMEM_TOTAL);

    int sm_count = 148;
    cudaDeviceGetAttribute(&sm_count, cudaDevAttrMultiProcessorCount, 0);

    build_comb_kernel<<<(COMB_N + 255) / 256, 256>>>(table);
    hashgrid1d_kernel<<<sm_count * 2, 1024, SMEM_TOTAL>>>(x, table, out, n);
}

// round 9
// speedup vs baseline: 1.5729x; 1.5729x over previous
#include <cuda_runtime.h>
#include <cuda.h>
#include <cuda_fp16.h>

// HashGrid1D on GB300 — R9.
// R7 compute structure (levels 0..8 pair-packed half4 in smem, level 9 half2
// in smem, levels 10+11 fused single gather) + TMA bulk-tensor store:
// each warp stages its 32 points (3KB) via SW128-swizzled conflict-free
// STS.128, one lane issues cp.async.bulk.tensor.2d (de-swizzled -> linear
// gmem). Removes LDS readback + STG wavefronts from the LSU entirely.
// Fallback (no tensormap encode available): exact R7 kernel.

#define HASH_MASK 16383
#define COMB_N    32769
#define SMEM_PAIRS 8185             // sum_{l=0}^{8} ((16<<l)+1)
#define L9_ENTRIES 8194
#define TBL_SCALE     16384.0f
#define TBL_INV_SCALE 6.103515625e-05f  // exact 2^-14
#define PAIR_BYTES  65488           // 8185*8 padded to 16
#define L9_BYTES    32784           // 8194*4 padded to 16
#define TBL_BYTES   (PAIR_BYTES + L9_BYTES)          // 98272

#define STAGE_BYTES (32 * 3072)                       // 98304 (32 warps x 3KB)
#define SMEM_TMA    (1024 + STAGE_BYTES + TBL_BYTES)  // 197600 (1KB align pad)

// R7 fallback smem: tables + stride-7 fp32 staging
#define FB_STAGE_OFF TBL_BYTES
#define SMEM_FB      (FB_STAGE_OFF + 1024 * 7 * 16)   // 212960

__device__ uint4 g_comb[COMB_N];   // {h2 e10[i10h], h2 e10[i10h+1], h2 e11[i11h], h2 e11[i11h+1]}

__device__ __forceinline__ unsigned pack_h2(float2 a)
{
    __half2 h = __floats2half2_rn(a.x * TBL_SCALE, a.y * TBL_SCALE);
    return *reinterpret_cast<unsigned*>(&h);
}

__device__ __forceinline__ float2 lerp_h2pair(unsigned u0, unsigned u1, float w)
{
    float2 e0 = __half22float2(*reinterpret_cast<__half2*>(&u0));
    float2 e1 = __half22float2(*reinterpret_cast<__half2*>(&u1));
    float2 r;
    r.x = fmaf(w, e1.x - e0.x, e0.x) * TBL_INV_SCALE;
    r.y = fmaf(w, e1.y - e0.y, e0.y) * TBL_INV_SCALE;
    return r;
}

__global__ void build_comb_kernel(const float* __restrict__ table)
{
    int j = blockIdx.x * blockDim.x + threadIdx.x;
    if (j >= COMB_N) return;
    int i10 = j >> 1;
    uint4 v;
    v.x = pack_h2(*reinterpret_cast<const float2*>(table + (i10 & HASH_MASK)       * 24 + 20));
    v.y = pack_h2(*reinterpret_cast<const float2*>(table + ((i10 + 1) & HASH_MASK) * 24 + 20));
    v.z = pack_h2(*reinterpret_cast<const float2*>(table + (j & HASH_MASK)         * 24 + 22));
    v.w = pack_h2(*reinterpret_cast<const float2*>(table + ((j + 1) & HASH_MASK)   * 24 + 22));
    g_comb[j] = v;
}

// shared table fill + per-point compute (24 fp32 outputs into o[6])
__device__ __forceinline__ void fill_tables(const float* __restrict__ table,
                                            uint2* spair, unsigned* s9)
{
    const int off[10] = {0, 17, 50, 115, 244, 501, 1014, 2039, 4088, 8185};
    for (int e = threadIdx.x; e < SMEM_PAIRS; e += blockDim.x) {
        int l = 0;
        #pragma unroll
        for (int k = 1; k < 9; ++k) l += (e >= off[k]);
        int i = e - off[l];
        uint2 v;
        v.x = pack_h2(*reinterpret_cast<const float2*>(table + i       * 24 + 2 * l));
        v.y = pack_h2(*reinterpret_cast<const float2*>(table + (i + 1) * 24 + 2 * l));
        spair[e] = v;
    }
    for (int i = threadIdx.x; i < L9_ENTRIES; i += blockDim.x)
        s9[i] = pack_h2(*reinterpret_cast<const float2*>(table + i * 24 + 18));
}

__device__ __forceinline__ void compute_point(float xv, const uint2* spair,
                                              const unsigned* s9, float4* o)
{
    const int off[10] = {0, 17, 50, 115, 244, 501, 1014, 2039, 4088, 8185};
    float xc = fminf(fmaxf(xv, 0.0f), 1.0f);

    float pos11 = xc * 32768.0f;
    int   i11   = __float2int_rd(pos11);
    uint4 g     = __ldg(&g_comb[i11]);

    float* of = reinterpret_cast<float*>(o);
    float res = 16.0f;
    #pragma unroll
    for (int l = 0; l < 9; ++l) {
        float pos = xc * res;
        int   i0  = __float2int_rd(pos);
        float w   = pos - (float)i0;
        uint2 v   = spair[off[l] + i0];
        float2 r  = lerp_h2pair(v.x, v.y, w);
        of[2 * l]     = r.x;
        of[2 * l + 1] = r.y;
        res *= 2.0f;
    }
    {
        float pos = xc * 8192.0f;
        int   i0  = __float2int_rd(pos);
        float w   = pos - (float)i0;
        float2 r  = lerp_h2pair(s9[i0], s9[i0 + 1], w);
        of[18] = r.x; of[19] = r.y;
    }
    {
        float pos10 = pos11 * 0.5f;
        int   i10   = i11 >> 1;
        float w10   = pos10 - (float)i10;
        float w11   = pos11 - (float)i11;
        float2 r  = lerp_h2pair(g.x, g.y, w10);
        of[20] = r.x; of[21] = r.y;
        r = lerp_h2pair(g.z, g.w, w11);
        of[22] = r.x; of[23] = r.y;
    }
}

// ---------------- TMA kernel ----------------
__global__ void __launch_bounds__(1024, 1)
hashgrid1d_tma_kernel(const float* __restrict__ x,
                      const float* __restrict__ table,
                      float* __restrict__ out, int n,
                      const __grid_constant__ CUtensorMap tmap)
{
    extern __shared__ unsigned char smem_raw[];
    unsigned sbase_s = (unsigned)__cvta_generic_to_shared(smem_raw);
    unsigned pad     = ((sbase_s + 1023u) & ~1023u) - sbase_s;   // 1024B-align staging
    unsigned char* stage_g = smem_raw + pad;
    unsigned stage_s = sbase_s + pad;
    uint2*    spair = reinterpret_cast<uint2*>(stage_g + STAGE_BYTES);
    unsigned* s9    = reinterpret_cast<unsigned*>(stage_g + STAGE_BYTES + PAIR_BYTES);

    fill_tables(table, spair, s9);
    __syncthreads();

    const int lane = threadIdx.x & 31;
    const int wid  = threadIdx.x >> 5;
    float4*  my_stage   = reinterpret_cast<float4*>(stage_g + wid * 3072);
    unsigned my_stage_s = stage_s + wid * 3072;

    int gwarp  = (blockIdx.x * blockDim.x + threadIdx.x) >> 5;
    int nwarps = (gridDim.x * blockDim.x) >> 5;
    int nfull  = n & ~31;

    for (int b0 = gwarp * 32; b0 < nfull; b0 += nwarps * 32) {
        float4 o[6];
        compute_point(x[b0 + lane], spair, s9, o);

        if (lane == 0)
            asm volatile("cp.async.bulk.wait_group.read 0;" ::: "memory");
        __syncwarp();

        // SW128-swizzled STS: u = 6*lane + j (16B units), s = u ^ ((u>>3)&7)
        #pragma unroll
        for (int j = 0; j < 6; ++j) {
            unsigned u = 6u * lane + j;
            unsigned s = u ^ ((u >> 3) & 7u);
            my_stage[s] = o[j];
        }
        __syncwarp();

        if (lane == 0) {
            asm volatile("fence.proxy.async.shared::cta;" ::: "memory");
            int row0 = (b0 >> 5) * 24;   // 96*b0/128
            asm volatile(
                "cp.async.bulk.tensor.2d.global.shared::cta.tile.bulk_group "
                "[%0, {%1, %2}], [%3];"
                :: "l"(&tmap), "r"(0), "r"(row0), "r"(my_stage_s) : "memory");
            asm volatile("cp.async.bulk.commit_group;" ::: "memory");
        }
    }
    if (lane == 0)
        asm volatile("cp.async.bulk.wait_group 0;" ::: "memory");

    // tail (n not multiple of 32): guarded direct stores
    for (int b = nfull + gwarp * 32 + lane; b < n; b += nwarps * 32) {
        float4 o[6];
        compute_point(x[b], spair, s9, o);
        float4* op = reinterpret_cast<float4*>(out + (size_t)b * 24);
        #pragma unroll
        for (int j = 0; j < 6; ++j) op[j] = o[j];
    }
}

// ---------------- fallback: exact R7 ----------------
__global__ void __launch_bounds__(1024, 1)
hashgrid1d_fb_kernel(const float* __restrict__ x,
                     const float* __restrict__ table,
                     float* __restrict__ out, int n)
{
    extern __shared__ unsigned char smem_raw[];
    uint2*    spair = reinterpret_cast<uint2*>(smem_raw);
    unsigned* s9    = reinterpret_cast<unsigned*>(smem_raw + PAIR_BYTES);
    float4*   stage = reinterpret_cast<float4*>(smem_raw + FB_STAGE_OFF);

    fill_tables(table, spair, s9);
    __syncthreads();

    const int lane = threadIdx.x & 31;
    float4* my_stage = stage + (threadIdx.x >> 5) * 224;

    int stride = gridDim.x * blockDim.x;
    for (int b = blockIdx.x * blockDim.x + threadIdx.x; b < n; b += stride) {
        float4 o[6];
        compute_point(x[b], spair, s9, o);

        #pragma unroll
        for (int j = 0; j < 6; ++j) my_stage[lane * 7 + j] = o[j];
        __syncwarp();

        float4* ob = reinterpret_cast<float4*>(out + (size_t)(b - lane) * 24);
        #pragma unroll
        for (int k = 0; k < 6; ++k) {
            int w4 = lane + 32 * k;
            int p  = (w4 * 2731) >> 14;
            int c  = w4 - p * 6;
            ob[w4] = my_stage[p * 7 + c];
        }
        __syncwarp();
    }
}

extern "C" void kernel_launch(void* const* d_in, const int* in_sizes, int n_in,
                              void* d_out, int out_size)
{
    const float* x     = (const float*)d_in[0];
    const float* table = (const float*)d_in[1];
    float*       out   = (float*)d_out;
    int n = in_sizes[0];
    int nfull = n & ~31;

    int sm_count = 148;
    cudaDeviceGetAttribute(&sm_count, cudaDevAttrMultiProcessorCount, 0);

    // Build the tensormap via the driver entry point (no -lcuda link needed).
    bool use_tma = false;
    CUtensorMap tmap;
    void* sym = nullptr;
    cudaDriverEntryPointQueryResult qres;
#if CUDART_VERSION >= 12050
    if (cudaGetDriverEntryPointByVersion("cuTensorMapEncodeTiled", &sym, 12000,
                                         cudaEnableDefault, &qres) != cudaSuccess)
        sym = nullptr;
#else
    if (cudaGetDriverEntryPoint("cuTensorMapEncodeTiled", &sym,
                                cudaEnableDefault, &qres) != cudaSuccess)
        sym = nullptr;
#endif
    if (sym && nfull > 0) {
        typedef CUresult (*Enc)(CUtensorMap*, CUtensorMapDataType, cuuint32_t, void*,
                                const cuuint64_t*, const cuuint64_t*,
                                const cuuint32_t*, const cuuint32_t*,
                                CUtensorMapInterleave, CUtensorMapSwizzle,
                                CUtensorMapL2promotion, CUtensorMapFloatOOBfill);
        Enc enc = (Enc)sym;
        // out viewed as 2D: rows of 128B (32 floats); nfull*24/32 rows total.
        cuuint64_t dims[2]    = {32ull, (cuuint64_t)(nfull / 32) * 24ull};
        cuuint64_t strides[1] = {128ull};
        cuuint32_t box[2]     = {32u, 24u};
        cuuint32_t estr[2]    = {1u, 1u};
        if (enc(&tmap, CU_TENSOR_MAP_DATA_TYPE_FLOAT32, 2, out,
                dims, strides, box, estr,
                CU_TENSOR_MAP_INTERLEAVE_NONE, CU_TENSOR_MAP_SWIZZLE_128B,
                CU_TENSOR_MAP_L2_PROMOTION_L2_128B,
                CU_TENSOR_MAP_FLOAT_OOB_FILL_NONE) == CUDA_SUCCESS)
            use_tma = true;
    }

    build_comb_kernel<<<(COMB_N + 255) / 256, 256>>>(table);

    if (use_tma) {
        cudaFuncSetAttribute(hashgrid1d_tma_kernel,
                             cudaFuncAttributeMaxDynamicSharedMemorySize, SMEM_TMA);
        hashgrid1d_tma_kernel<<<sm_count, 1024, SMEM_TMA>>>(x, table, out, n, tmap);
    } else {
        cudaFuncSetAttribute(hashgrid1d_fb_kernel,
                             cudaFuncAttributeMaxDynamicSharedMemorySize, SMEM_FB);
        hashgrid1d_fb_kernel<<<sm_count, 1024, SMEM_FB>>>(x, table, out, n);
    }
}